// round 16
// baseline (speedup 1.0000x reference)
#include <cuda_runtime.h>

#define DIM     1024
#define NPAIRS  512
#define NLAYER  10
#define NACTIVE 2044   // params for layers 1..9: 2*sum(DIM>>l, l=1..9)

// Single kernel, grid = rows/16, 8 warps per CTA, TWO rows per warp.
//
// Math: with base point 0 both Mobius maps are radial scalings
//   log0(x) = atanh(|x|)/|x| x,  exp0(v) = tanh(|v|)/|v| v,
// and the butterfly always pairs adjacent elements (2k,2k+1), acting as
// [[a,b],[-b,a]] = complex multiply by (a - ib): one composite W_k per pair,
//   |butterfly(u)|^2 = s1^2 * sum_k |W_k|^2 (x_{2k}^2 + x_{2k+1}^2).
//
// R16 change: 2 rows per warp. The per-row serial phase (10-deep shuffle
// chain + transcendentals) starved the LSU at 44.7% occupancy; processing
// rows A+B per warp doubles outstanding loads (16 LDG.128) and amortizes one
// interleaved 5-round shuffle chain (4 independent values/round) over 2 rows.
// Two-pass per row is kept so no x register array lives across the reduction.
__global__ void __launch_bounds__(256, 4)
hyper_butterfly_2row(const float* __restrict__ x,
                     const float* __restrict__ params,
                     float* __restrict__ out) {
    __shared__ __align__(16) float buf[2048];      // 8 KB, reused

    const int t    = threadIdx.x;
    const int warp = t >> 5;
    const int lane = t & 31;

    // ── Prologue A: coalesced batch-load of active params.
#pragma unroll
    for (int j = 0; j < 8; ++j) {
        int i = t + 256 * j;
        if (i < NACTIVE) buf[i] = params[2 * DIM + i];
    }
    __syncthreads();

    // ── Prologue B: compose W for pairs t and t+256, keep in registers.
    float A[2], B[2];
#pragma unroll
    for (int h = 0; h < 2; ++h) {
        const int k = t + h * 256;
        float a0 = 1.0f, b0 = 0.0f;
        int off = 0;
#pragma unroll
        for (int l = 1; l < NLAYER; ++l) {
            const int blk = k >> (l - 1);
            const float a = buf[off + 2 * blk];
            const float b = buf[off + 2 * blk + 1];
            const float na = a0 * a + b0 * b;      // (a0+ib0)*(a-ib)
            const float nb = b0 * a - a0 * b;
            a0 = na; b0 = nb;
            off += 2 * (DIM >> l);
        }
        A[h] = a0; B[h] = b0;
    }
    __syncthreads();   // all param reads done before buffer reuse

    // ── Prologue C: write W tables into the reused buffer.
    //   buf[0..1023]    = float2 W_k (as float4 per 2-pair chunk)
    //   buf[1024..1535] = |W_k|^2 (as float2 per chunk)
#pragma unroll
    for (int h = 0; h < 2; ++h) {
        const int k = t + h * 256;
        reinterpret_cast<float2*>(buf)[k] = make_float2(A[h], B[h]);
        buf[1024 + k] = A[h] * A[h] + B[h] * B[h];
    }
    __syncthreads();

    const float4* __restrict__ sW4 = reinterpret_cast<const float4*>(buf);
    const float2* __restrict__ sZ  = reinterpret_cast<const float2*>(buf + 1024);

    const int rowA = (blockIdx.x << 4) + 2 * warp;     // rows rowA, rowA+1
    const float4* __restrict__ xrA = reinterpret_cast<const float4*>(x + (size_t)rowA * DIM);
    const float4* __restrict__ xrB = xrA + (DIM / 4);
    float4* __restrict__ orA       = reinterpret_cast<float4*>(out + (size_t)rowA * DIM);
    float4* __restrict__ orB       = orA + (DIM / 4);

    // ── Pass 1: stream both rows, accumulate 4 norm partials.
    float r0A = 0.0f, r1A = 0.0f, r0B = 0.0f, r1B = 0.0f;
#pragma unroll
    for (int j = 0; j < 8; ++j) {
        const int c = lane + 32 * j;
        const float4 xa = xrA[c];
        const float4 xb = xrB[c];
        const float2 wz = sZ[c];
        const float qa0 = xa.x * xa.x + xa.y * xa.y;
        const float qa1 = xa.z * xa.z + xa.w * xa.w;
        const float qb0 = xb.x * xb.x + xb.y * xb.y;
        const float qb1 = xb.z * xb.z + xb.w * xb.w;
        r0A += qa0 + qa1;
        r1A += wz.x * qa0 + wz.y * qa1;
        r0B += qb0 + qb1;
        r1B += wz.x * qb0 + wz.y * qb1;
    }

    // Interleaved warp reduce: 4 independent shuffle+add pairs per round,
    // one 5-round latency chain amortized over both rows.
#pragma unroll
    for (int o = 16; o; o >>= 1) {
        r0A += __shfl_xor_sync(0xffffffffu, r0A, o);
        r1A += __shfl_xor_sync(0xffffffffu, r1A, o);
        r0B += __shfl_xor_sync(0xffffffffu, r0B, o);
        r1B += __shfl_xor_sync(0xffffffffu, r1B, o);
    }

    const float nA2 = sqrtf(r0A);
    const float s1A = atanhf(nA2) / fmaxf(nA2, 1e-12f);
    const float mA  = s1A * sqrtf(r1A);
    const float sA  = s1A * tanhf(mA) / fmaxf(mA, 1e-12f);

    const float nB2 = sqrtf(r0B);
    const float s1B = atanhf(nB2) / fmaxf(nB2, 1e-12f);
    const float mB  = s1B * sqrtf(r1B);
    const float sB  = s1B * tanhf(mB) / fmaxf(mB, 1e-12f);

    // Force pass 2 to genuinely reload x (L1/L2 hit) instead of keeping
    // x registers live across the reduction.
    asm volatile("" ::: "memory");

    // ── Pass 2: reload both rows, rotate, scale, streaming-store.
#pragma unroll
    for (int j = 0; j < 8; ++j) {
        const int c = lane + 32 * j;
        const float4 w  = sW4[c];
        const float4 xa = xrA[c];
        float4 oa;
        oa.x = sA * (w.x * xa.x - w.y * xa.y);
        oa.y = sA * (w.x * xa.y + w.y * xa.x);
        oa.z = sA * (w.z * xa.z - w.w * xa.w);
        oa.w = sA * (w.z * xa.w + w.w * xa.z);
        __stcs(orA + c, oa);

        const float4 xb = xrB[c];
        float4 ob;
        ob.x = sB * (w.x * xb.x - w.y * xb.y);
        ob.y = sB * (w.x * xb.y + w.y * xb.x);
        ob.z = sB * (w.z * xb.z - w.w * xb.w);
        ob.w = sB * (w.z * xb.w + w.w * xb.z);
        __stcs(orB + c, ob);
    }
}

extern "C" void kernel_launch(void* const* d_in, const int* in_sizes, int n_in,
                              void* d_out, int out_size) {
    const float* x      = (const float*)d_in[0];
    const float* params = (const float*)d_in[1];
    float* out          = (float*)d_out;

    const int rows = in_sizes[0] / DIM;   // 32768
    hyper_butterfly_2row<<<rows >> 4, 256>>>(x, params, out);
}